// round 1
// baseline (speedup 1.0000x reference)
#include <cuda_runtime.h>
#include <math.h>
#include <stdint.h>

#define N_NODES 50000
#define E_MAX   500000

// ---------------- scratch (static __device__ — no allocations allowed) -------
__device__ float g_bufA[(size_t)N_NODES * 512];
__device__ float g_bufB[(size_t)N_NODES * 512 + 64];
__device__ float g_el[(size_t)N_NODES * 8];
__device__ float g_er[(size_t)N_NODES * 8];
__device__ int   g_deg[N_NODES];
__device__ int   g_off[N_NODES + 1];
__device__ int   g_pos[N_NODES];
__device__ int   g_esrc[E_MAX + 8];

// ---------------- CSR build ---------------------------------------------------
__global__ void zero_deg_kernel() {
    int i = blockIdx.x * blockDim.x + threadIdx.x;
    if (i < N_NODES) g_deg[i] = 0;
}

__global__ void hist_kernel(const int* __restrict__ dst, int E) {
    int i = blockIdx.x * blockDim.x + threadIdx.x;
    if (i < E) atomicAdd(&g_deg[dst[i]], 1);
}

// single-block exclusive scan of g_deg -> g_off (and copy to g_pos)
__global__ void scan_kernel(int n) {
    __shared__ int wsum[32];
    __shared__ int s_carry;
    int tid = threadIdx.x;
    int lane = tid & 31, wid = tid >> 5;
    if (tid == 0) s_carry = 0;
    __syncthreads();
    for (int base = 0; base < n; base += blockDim.x) {
        int i = base + tid;
        int v = (i < n) ? g_deg[i] : 0;
        int x = v;
        #pragma unroll
        for (int o = 1; o < 32; o <<= 1) {
            int y = __shfl_up_sync(0xffffffffu, x, o);
            if (lane >= o) x += y;
        }
        if (lane == 31) wsum[wid] = x;
        __syncthreads();
        if (wid == 0) {
            int w = wsum[lane];
            #pragma unroll
            for (int o = 1; o < 32; o <<= 1) {
                int y = __shfl_up_sync(0xffffffffu, w, o);
                if (lane >= o) w += y;
            }
            wsum[lane] = w;
        }
        __syncthreads();
        int incl = x + (wid > 0 ? wsum[wid - 1] : 0);
        int c = s_carry;
        if (i < n) {
            int ex = c + incl - v;
            g_off[i] = ex;
            g_pos[i] = ex;
        }
        __syncthreads();
        if (tid == 0) s_carry = c + wsum[31];
        __syncthreads();
    }
    if (tid == 0) g_off[n] = s_carry;
}

__global__ void scatter_kernel(const int* __restrict__ src, const int* __restrict__ dst, int E) {
    int i = blockIdx.x * blockDim.x + threadIdx.x;
    if (i < E) {
        int p = atomicAdd(&g_pos[dst[i]], 1);
        g_esrc[p] = src[i];
    }
}

// ---------------- fp32 tiled GEMM: C[M,N] = A[M,K] @ B[K,N] (+bias) ----------
// BM=128 BN=128 BK=8, 256 threads, 8x8 per thread. K % 8 == 0 and N % 4 == 0 assumed.
__global__ __launch_bounds__(256) void gemm128(const float* __restrict__ A,
                                               const float* __restrict__ B,
                                               const float* __restrict__ bias,
                                               float* __restrict__ C,
                                               int M, int N, int K) {
    __shared__ float As[8][128];
    __shared__ float Bs[8][128];
    int bm = blockIdx.y * 128;
    int bn = blockIdx.x * 128;
    int tid = threadIdx.x;
    int tcol = tid & 15;   // 0..15
    int trow = tid >> 4;   // 0..15

    int arow = tid >> 1;          // 0..127
    int acol = (tid & 1) * 4;     // 0 or 4
    int brow = tid >> 5;          // 0..7
    int bcol = (tid & 31) * 4;    // 0..124

    float acc[8][8];
    #pragma unroll
    for (int i = 0; i < 8; i++)
        #pragma unroll
        for (int j = 0; j < 8; j++) acc[i][j] = 0.0f;

    for (int k0 = 0; k0 < K; k0 += 8) {
        float4 av = make_float4(0.f, 0.f, 0.f, 0.f);
        if (bm + arow < M)
            av = *(const float4*)&A[(size_t)(bm + arow) * K + k0 + acol];
        As[acol + 0][arow] = av.x;
        As[acol + 1][arow] = av.y;
        As[acol + 2][arow] = av.z;
        As[acol + 3][arow] = av.w;
        float4 bv = make_float4(0.f, 0.f, 0.f, 0.f);
        if (bn + bcol < N)
            bv = *(const float4*)&B[(size_t)(k0 + brow) * N + bn + bcol];
        *(float4*)&Bs[brow][bcol] = bv;
        __syncthreads();
        #pragma unroll
        for (int k = 0; k < 8; ++k) {
            float4 a0 = *(float4*)&As[k][trow * 8];
            float4 a1 = *(float4*)&As[k][trow * 8 + 4];
            float4 b0 = *(float4*)&Bs[k][tcol * 8];
            float4 b1 = *(float4*)&Bs[k][tcol * 8 + 4];
            float ra[8] = {a0.x, a0.y, a0.z, a0.w, a1.x, a1.y, a1.z, a1.w};
            float rb[8] = {b0.x, b0.y, b0.z, b0.w, b1.x, b1.y, b1.z, b1.w};
            #pragma unroll
            for (int i = 0; i < 8; i++)
                #pragma unroll
                for (int j = 0; j < 8; j++)
                    acc[i][j] += ra[i] * rb[j];
        }
        __syncthreads();
    }
    #pragma unroll
    for (int i = 0; i < 8; i++) {
        int r = bm + trow * 8 + i;
        if (r >= M) continue;
        #pragma unroll
        for (int j = 0; j < 8; j++) {
            int c = bn + tcol * 8 + j;
            if (c < N) {
                float v = acc[i][j];
                if (bias) v += bias[c];
                C[(size_t)r * N + c] = v;
            }
        }
    }
}

// ---------------- attention projections: el/er = <ft[n,h,:], al/ar[h,:]> -----
__global__ void attn_proj_kernel(const float* __restrict__ ft,
                                 const float* __restrict__ al,
                                 const float* __restrict__ ar,
                                 float* __restrict__ el, float* __restrict__ er,
                                 int N, int H, int D) {
    int gw = (blockIdx.x * blockDim.x + threadIdx.x) >> 5;
    int lane = threadIdx.x & 31;
    if (gw >= N * H) return;
    int n = gw / H, h = gw % H;
    const float* f = ft + ((size_t)n * H + h) * D;
    float sl = 0.f, sr = 0.f;
    for (int d = lane; d < D; d += 32) {
        float v = f[d];
        sl += v * al[h * D + d];
        sr += v * ar[h * D + d];
    }
    #pragma unroll
    for (int o = 16; o; o >>= 1) {
        sl += __shfl_xor_sync(0xffffffffu, sl, o);
        sr += __shfl_xor_sync(0xffffffffu, sr, o);
    }
    if (lane == 0) {
        el[(size_t)n * H + h] = sl;
        er[(size_t)n * H + h] = sr;
    }
}

__device__ __forceinline__ float lrelu(float x) { return x > 0.f ? x : 0.2f * x; }

// ---------------- GAT aggregation, H=8 D=64, one block per dst node ----------
// RES = 0: none, 1: identity residual from hres[N,512]. act = ELU always.
template <int RES>
__global__ __launch_bounds__(256) void gat_agg_h8(const float* __restrict__ ft,
                                                  const float* __restrict__ el,
                                                  const float* __restrict__ er,
                                                  const float* __restrict__ bias,
                                                  const float* __restrict__ hres,
                                                  float* __restrict__ out) {
    int n = blockIdx.x;
    int h = threadIdx.x >> 5;
    int lane = threadIdx.x & 31;
    int s = g_off[n], e = g_off[n + 1];
    float ern = er[(size_t)n * 8 + h];

    float m = -INFINITY;
    for (int i = s + lane; i < e; i += 32)
        m = fmaxf(m, lrelu(el[(size_t)g_esrc[i] * 8 + h] + ern));
    #pragma unroll
    for (int o = 16; o; o >>= 1) m = fmaxf(m, __shfl_xor_sync(0xffffffffu, m, o));

    float ss = 0.f;
    for (int i = s + lane; i < e; i += 32)
        ss += expf(lrelu(el[(size_t)g_esrc[i] * 8 + h] + ern) - m);
    #pragma unroll
    for (int o = 16; o; o >>= 1) ss += __shfl_xor_sync(0xffffffffu, ss, o);
    float inv = (e > s) ? 1.0f / ss : 0.0f;

    float a0 = 0.f, a1 = 0.f;
    for (int i = s; i < e; ++i) {
        int sn = g_esrc[i];
        float a = expf(lrelu(el[(size_t)sn * 8 + h] + ern) - m) * inv;
        const float* fr = ft + ((size_t)sn * 8 + h) * 64;
        a0 += a * fr[lane];
        a1 += a * fr[lane + 32];
    }
    int c0 = h * 64 + lane;
    int c1 = c0 + 32;
    float v0 = a0 + bias[c0];
    float v1 = a1 + bias[c1];
    if (RES) {
        v0 += hres[(size_t)n * 512 + c0];
        v1 += hres[(size_t)n * 512 + c1];
    }
    v0 = v0 > 0.f ? v0 : expm1f(v0);
    v1 = v1 > 0.f ? v1 : expm1f(v1);
    out[(size_t)n * 512 + c0] = v0;
    out[(size_t)n * 512 + c1] = v1;
}

// ---------------- layer-2 fused GEMM: ft2 = h@W (16), res2 = h@Wres (16) -----
__global__ __launch_bounds__(256) void gemm_l2_kernel(const float* __restrict__ h,
                                                      const float* __restrict__ W,
                                                      const float* __restrict__ Wr,
                                                      float* __restrict__ ft,
                                                      float* __restrict__ res) {
    __shared__ float sh[512];
    int n = blockIdx.x;
    const float* row = h + (size_t)n * 512;
    for (int i = threadIdx.x; i < 512; i += 256) sh[i] = row[i];
    __syncthreads();
    int wid = threadIdx.x >> 5, lane = threadIdx.x & 31;
    int jbase = wid * 4;  // warps 0..3 -> ft cols 0..15, warps 4..7 -> res cols
    float p[4] = {0.f, 0.f, 0.f, 0.f};
    for (int k = lane; k < 512; k += 32) {
        float hv = sh[k];
        #pragma unroll
        for (int jj = 0; jj < 4; jj++) {
            int j = jbase + jj;
            float w = (j < 16) ? W[k * 16 + j] : Wr[k * 16 + (j - 16)];
            p[jj] += hv * w;
        }
    }
    #pragma unroll
    for (int jj = 0; jj < 4; jj++) {
        float v = p[jj];
        #pragma unroll
        for (int o = 16; o; o >>= 1) v += __shfl_xor_sync(0xffffffffu, v, o);
        if (lane == 0) {
            int j = jbase + jj;
            if (j < 16) ft[(size_t)n * 16 + j] = v;
            else        res[(size_t)n * 16 + (j - 16)] = v;
        }
    }
}

// ---------------- layer-2 aggregation: H=1 D=16, one warp per node -----------
__global__ void gat_agg_l2(const float* __restrict__ ft,
                           const float* __restrict__ el,
                           const float* __restrict__ er,
                           const float* __restrict__ res,
                           const float* __restrict__ bias,
                           float* __restrict__ out) {
    int node = blockIdx.x * 8 + (threadIdx.x >> 5);
    if (node >= N_NODES) return;
    int lane = threadIdx.x & 31;
    int s = g_off[node], e = g_off[node + 1];
    float ern = er[node];

    float m = -INFINITY;
    for (int i = s + lane; i < e; i += 32)
        m = fmaxf(m, lrelu(el[g_esrc[i]] + ern));
    #pragma unroll
    for (int o = 16; o; o >>= 1) m = fmaxf(m, __shfl_xor_sync(0xffffffffu, m, o));

    float ss = 0.f;
    for (int i = s + lane; i < e; i += 32)
        ss += expf(lrelu(el[g_esrc[i]] + ern) - m);
    #pragma unroll
    for (int o = 16; o; o >>= 1) ss += __shfl_xor_sync(0xffffffffu, ss, o);
    float inv = (e > s) ? 1.0f / ss : 0.0f;

    float acc = 0.f;
    for (int i = s; i < e; ++i) {
        int sn = g_esrc[i];
        float a = expf(lrelu(el[sn] + ern) - m) * inv;
        if (lane < 16) acc += a * ft[(size_t)sn * 16 + lane];
    }
    if (lane < 16)
        out[(size_t)node * 16 + lane] = acc + res[(size_t)node * 16 + lane] + bias[lane];
}

// ---------------- launcher ----------------------------------------------------
extern "C" void kernel_launch(void* const* d_in, const int* in_sizes, int n_in,
                              void* d_out, int out_size) {
    const float* feat0 = (const float*)d_in[0];
    const float* feat1 = (const float*)d_in[1];
    const float* fc0_w = (const float*)d_in[2];
    const float* fc0_b = (const float*)d_in[3];
    const float* fc1_w = (const float*)d_in[4];
    const float* fc1_b = (const float*)d_in[5];
    const float* l0_W  = (const float*)d_in[6];
    const float* l0_al = (const float*)d_in[7];
    const float* l0_ar = (const float*)d_in[8];
    const float* l0_b  = (const float*)d_in[9];
    const float* l1_W  = (const float*)d_in[10];
    const float* l1_al = (const float*)d_in[11];
    const float* l1_ar = (const float*)d_in[12];
    const float* l1_b  = (const float*)d_in[13];
    const float* l2_W  = (const float*)d_in[14];
    const float* l2_al = (const float*)d_in[15];
    const float* l2_ar = (const float*)d_in[16];
    const float* l2_b  = (const float*)d_in[17];
    const float* l2_rw = (const float*)d_in[18];
    const int*   src   = (const int*)d_in[19];
    const int*   dst   = (const int*)d_in[20];
    int E = in_sizes[19];

    float* pA;
    float* pB;
    float* pel;
    float* per;
    cudaGetSymbolAddress((void**)&pA, g_bufA);
    cudaGetSymbolAddress((void**)&pB, g_bufB);
    cudaGetSymbolAddress((void**)&pel, g_el);
    cudaGetSymbolAddress((void**)&per, g_er);

    float* logits = (float*)d_out;
    const size_t LOGITS = (size_t)N_NODES * 16;
    const size_t ENC    = (size_t)N_NODES * 512;
    float* encoded = ((size_t)out_size >= LOGITS + ENC) ? logits + LOGITS : pA;

    // --- CSR build ---
    zero_deg_kernel<<<(N_NODES + 255) / 256, 256>>>();
    hist_kernel<<<(E + 255) / 256, 256>>>(dst, E);
    scan_kernel<<<1, 1024>>>(N_NODES);
    scatter_kernel<<<(E + 255) / 256, 256>>>(src, dst, E);

    // --- input projections: bufA[0:25000,64] and bufA[25000:50000,64] ---
    {
        dim3 g0(1, (25000 + 127) / 128);
        gemm128<<<g0, 256>>>(feat0, fc0_w, fc0_b, pA, 25000, 64, 256);
        gemm128<<<g0, 256>>>(feat1, fc1_w, fc1_b, pA + (size_t)25000 * 64, 25000, 64, 256);
    }

    dim3 gBig(4, (N_NODES + 127) / 128);  // N=512 tiles x M tiles

    // --- layer 0: ft = h @ l0_W ; agg (no residual, ELU) -> bufA[N,512] ---
    gemm128<<<gBig, 256>>>(pA, l0_W, nullptr, pB, N_NODES, 512, 64);
    attn_proj_kernel<<<(N_NODES * 8 + 7) / 8, 256>>>(pB, l0_al, l0_ar, pel, per, N_NODES, 8, 64);
    gat_agg_h8<0><<<N_NODES, 256>>>(pB, pel, per, l0_b, nullptr, pA);

    // --- layer 1: ft = h @ l1_W ; agg (identity residual, ELU) -> encoded ---
    gemm128<<<gBig, 256>>>(pA, l1_W, nullptr, pB, N_NODES, 512, 512);
    attn_proj_kernel<<<(N_NODES * 8 + 7) / 8, 256>>>(pB, l1_al, l1_ar, pel, per, N_NODES, 8, 64);
    gat_agg_h8<1><<<N_NODES, 256>>>(pB, pel, per, l1_b, pA, encoded);

    // --- layer 2: ft2/res2 from encoded; agg (linear residual, no act) -> logits ---
    float* ft2  = pB;
    float* res2 = pB + LOGITS;
    gemm_l2_kernel<<<N_NODES, 256>>>(encoded, l2_W, l2_rw, ft2, res2);
    attn_proj_kernel<<<(N_NODES + 7) / 8, 256>>>(ft2, l2_al, l2_ar, pel, per, N_NODES, 1, 16);
    gat_agg_l2<<<(N_NODES + 7) / 8, 256>>>(ft2, pel, per, res2, l2_b, logits);
}

// round 2
// speedup vs baseline: 1.1562x; 1.1562x over previous
#include <cuda_runtime.h>
#include <math.h>
#include <stdint.h>

#define N_NODES 50000
#define E_MAX   500000

// ---------------- scratch (static __device__ — no allocations allowed) -------
__device__ float g_bufA[(size_t)N_NODES * 512];
__device__ float g_bufB[(size_t)N_NODES * 512 + 64];
__device__ float g_el[(size_t)N_NODES * 8];
__device__ float g_er[(size_t)N_NODES * 8];
__device__ int   g_deg[N_NODES];
__device__ int   g_off[N_NODES + 1];
__device__ int   g_pos[N_NODES];
__device__ int   g_esrc[E_MAX + 8];

// ---------------- CSR build ---------------------------------------------------
__global__ void zero_deg_kernel() {
    int i = blockIdx.x * blockDim.x + threadIdx.x;
    if (i < N_NODES) g_deg[i] = 0;
}

__global__ void hist_kernel(const int* __restrict__ dst, int E) {
    int i = blockIdx.x * blockDim.x + threadIdx.x;
    if (i < E) atomicAdd(&g_deg[dst[i]], 1);
}

// single-block exclusive scan of g_deg -> g_off (and copy to g_pos)
__global__ void scan_kernel(int n) {
    __shared__ int wsum[32];
    __shared__ int s_carry;
    int tid = threadIdx.x;
    int lane = tid & 31, wid = tid >> 5;
    if (tid == 0) s_carry = 0;
    __syncthreads();
    for (int base = 0; base < n; base += blockDim.x) {
        int i = base + tid;
        int v = (i < n) ? g_deg[i] : 0;
        int x = v;
        #pragma unroll
        for (int o = 1; o < 32; o <<= 1) {
            int y = __shfl_up_sync(0xffffffffu, x, o);
            if (lane >= o) x += y;
        }
        if (lane == 31) wsum[wid] = x;
        __syncthreads();
        if (wid == 0) {
            int w = wsum[lane];
            #pragma unroll
            for (int o = 1; o < 32; o <<= 1) {
                int y = __shfl_up_sync(0xffffffffu, w, o);
                if (lane >= o) w += y;
            }
            wsum[lane] = w;
        }
        __syncthreads();
        int incl = x + (wid > 0 ? wsum[wid - 1] : 0);
        int c = s_carry;
        if (i < n) {
            int ex = c + incl - v;
            g_off[i] = ex;
            g_pos[i] = ex;
        }
        __syncthreads();
        if (tid == 0) s_carry = c + wsum[31];
        __syncthreads();
    }
    if (tid == 0) g_off[n] = s_carry;
}

__global__ void scatter_kernel(const int* __restrict__ src, const int* __restrict__ dst, int E) {
    int i = blockIdx.x * blockDim.x + threadIdx.x;
    if (i < E) {
        int p = atomicAdd(&g_pos[dst[i]], 1);
        g_esrc[p] = src[i];
    }
}

// ---------------- tf32 tensor-core GEMM: C[M,N] = A[M,K]@B[K,N] (+bias) -------
// BM=128 BN=128 BK=16, 256 threads = 8 warps (2x4 warp grid, warp tile 64x32).
// mma.sync.aligned.m16n8k8.row.col.f32.tf32.tf32.f32, RNA tf32 conversion on
// the global->shared path. Requires K%16==0, N%4==0.
__device__ __forceinline__ uint32_t f2tf32(float x) {
    uint32_t r;
    asm("cvt.rna.tf32.f32 %0, %1;" : "=r"(r) : "f"(x));
    return r;
}

__global__ __launch_bounds__(256) void gemm_tf32(const float* __restrict__ A,
                                                 const float* __restrict__ B,
                                                 const float* __restrict__ bias,
                                                 float* __restrict__ C,
                                                 int M, int N, int K) {
    __shared__ uint32_t As[16][132];  // [k][m], +4 pad
    __shared__ uint32_t Bs[16][132];  // [k][n], +4 pad
    int bm = blockIdx.y * 128;
    int bn = blockIdx.x * 128;
    int tid = threadIdx.x;
    int warp = tid >> 5, lane = tid & 31;
    int wm = (warp & 1) * 64;    // warp row base within block tile
    int wn = (warp >> 1) * 32;   // warp col base within block tile
    int g = lane >> 2, tg = lane & 3;

    float acc[4][4][4];
    #pragma unroll
    for (int i = 0; i < 4; i++)
        #pragma unroll
        for (int j = 0; j < 4; j++)
            #pragma unroll
            for (int r = 0; r < 4; r++) acc[i][j][r] = 0.0f;

    for (int k0 = 0; k0 < K; k0 += 16) {
        // load A tile: 128 rows x 16 cols = 512 float4, 2 per thread
        #pragma unroll
        for (int i = 0; i < 2; i++) {
            int idx = tid * 2 + i;
            int r = idx >> 2;           // 0..127
            int c4 = (idx & 3) * 4;     // 0,4,8,12
            float4 av = make_float4(0.f, 0.f, 0.f, 0.f);
            if (bm + r < M)
                av = *(const float4*)&A[(size_t)(bm + r) * K + k0 + c4];
            As[c4 + 0][r] = f2tf32(av.x);
            As[c4 + 1][r] = f2tf32(av.y);
            As[c4 + 2][r] = f2tf32(av.z);
            As[c4 + 3][r] = f2tf32(av.w);
        }
        // load B tile: 16 rows x 128 cols = 512 float4, 2 per thread
        #pragma unroll
        for (int i = 0; i < 2; i++) {
            int idx = tid * 2 + i;
            int r = idx >> 5;           // 0..15
            int c4 = (idx & 31) * 4;    // 0..124
            float4 bv = make_float4(0.f, 0.f, 0.f, 0.f);
            if (bn + c4 < N)
                bv = *(const float4*)&B[(size_t)(k0 + r) * N + bn + c4];
            Bs[r][c4 + 0] = f2tf32(bv.x);
            Bs[r][c4 + 1] = f2tf32(bv.y);
            Bs[r][c4 + 2] = f2tf32(bv.z);
            Bs[r][c4 + 3] = f2tf32(bv.w);
        }
        __syncthreads();
        #pragma unroll
        for (int kk = 0; kk < 16; kk += 8) {
            uint32_t af[4][4];
            #pragma unroll
            for (int mt = 0; mt < 4; mt++) {
                int rb = wm + mt * 16;
                af[mt][0] = As[kk + tg][rb + g];
                af[mt][1] = As[kk + tg][rb + g + 8];
                af[mt][2] = As[kk + tg + 4][rb + g];
                af[mt][3] = As[kk + tg + 4][rb + g + 8];
            }
            uint32_t bf[4][2];
            #pragma unroll
            for (int nt = 0; nt < 4; nt++) {
                int cb = wn + nt * 8;
                bf[nt][0] = Bs[kk + tg][cb + g];
                bf[nt][1] = Bs[kk + tg + 4][cb + g];
            }
            #pragma unroll
            for (int mt = 0; mt < 4; mt++)
                #pragma unroll
                for (int nt = 0; nt < 4; nt++) {
                    asm volatile(
                        "mma.sync.aligned.m16n8k8.row.col.f32.tf32.tf32.f32 "
                        "{%0,%1,%2,%3}, {%4,%5,%6,%7}, {%8,%9}, {%0,%1,%2,%3};"
                        : "+f"(acc[mt][nt][0]), "+f"(acc[mt][nt][1]),
                          "+f"(acc[mt][nt][2]), "+f"(acc[mt][nt][3])
                        : "r"(af[mt][0]), "r"(af[mt][1]), "r"(af[mt][2]), "r"(af[mt][3]),
                          "r"(bf[nt][0]), "r"(bf[nt][1]));
                }
        }
        __syncthreads();
    }
    // store: c0 (row g, col 2tg), c1 (row g, col 2tg+1), c2/c3 (+8 rows)
    #pragma unroll
    for (int mt = 0; mt < 4; mt++) {
        #pragma unroll
        for (int nt = 0; nt < 4; nt++) {
            int r0 = bm + wm + mt * 16 + g;
            int c0 = bn + wn + nt * 8 + 2 * tg;
            #pragma unroll
            for (int hh = 0; hh < 2; hh++) {  // row offset 0 / +8
                int r = r0 + hh * 8;
                if (r >= M) continue;
                #pragma unroll
                for (int cc = 0; cc < 2; cc++) {
                    int c = c0 + cc;
                    if (c < N) {
                        float v = acc[mt][nt][hh * 2 + cc];
                        if (bias) v += bias[c];
                        C[(size_t)r * N + c] = v;
                    }
                }
            }
        }
    }
}

// ---------------- attention projections: el/er = <ft[n,h,:], al/ar[h,:]> -----
__global__ void attn_proj_kernel(const float* __restrict__ ft,
                                 const float* __restrict__ al,
                                 const float* __restrict__ ar,
                                 float* __restrict__ el, float* __restrict__ er,
                                 int N, int H, int D) {
    int gw = (blockIdx.x * blockDim.x + threadIdx.x) >> 5;
    int lane = threadIdx.x & 31;
    if (gw >= N * H) return;
    int n = gw / H, h = gw % H;
    const float* f = ft + ((size_t)n * H + h) * D;
    float sl = 0.f, sr = 0.f;
    for (int d = lane; d < D; d += 32) {
        float v = f[d];
        sl += v * al[h * D + d];
        sr += v * ar[h * D + d];
    }
    #pragma unroll
    for (int o = 16; o; o >>= 1) {
        sl += __shfl_xor_sync(0xffffffffu, sl, o);
        sr += __shfl_xor_sync(0xffffffffu, sr, o);
    }
    if (lane == 0) {
        el[(size_t)n * H + h] = sl;
        er[(size_t)n * H + h] = sr;
    }
}

__device__ __forceinline__ float lrelu(float x) { return x > 0.f ? x : 0.2f * x; }

// ---------------- GAT aggregation, H=8 D=64, one block per dst node ----------
// Online softmax: single pass computes (max, sum), then weighted gather pass.
template <int RES>
__global__ __launch_bounds__(256) void gat_agg_h8(const float* __restrict__ ft,
                                                  const float* __restrict__ el,
                                                  const float* __restrict__ er,
                                                  const float* __restrict__ bias,
                                                  const float* __restrict__ hres,
                                                  float* __restrict__ out) {
    int n = blockIdx.x;
    int h = threadIdx.x >> 5;
    int lane = threadIdx.x & 31;
    int s = g_off[n], e = g_off[n + 1];
    float ern = er[(size_t)n * 8 + h];

    // online (m, s) per lane
    float m = -INFINITY, ss = 0.f;
    for (int i = s + lane; i < e; i += 32) {
        float v = lrelu(el[(size_t)g_esrc[i] * 8 + h] + ern);
        float mn = fmaxf(m, v);
        ss = ss * expf(m - mn) + expf(v - mn);
        m = mn;
    }
    #pragma unroll
    for (int o = 16; o; o >>= 1) {
        float om = __shfl_xor_sync(0xffffffffu, m, o);
        float os = __shfl_xor_sync(0xffffffffu, ss, o);
        float mn = fmaxf(m, om);
        // guard: both -inf -> keep 0 contributions, avoid NaN
        float sa = (m == -INFINITY) ? 0.f : ss * expf(m - mn);
        float sb = (om == -INFINITY) ? 0.f : os * expf(om - mn);
        ss = sa + sb;
        m = mn;
    }
    float inv = (e > s) ? 1.0f / ss : 0.0f;

    float a0 = 0.f, a1 = 0.f;
    for (int i = s; i < e; ++i) {
        int sn = g_esrc[i];
        float a = expf(lrelu(el[(size_t)sn * 8 + h] + ern) - m) * inv;
        const float* fr = ft + ((size_t)sn * 8 + h) * 64;
        a0 += a * fr[lane];
        a1 += a * fr[lane + 32];
    }
    int c0 = h * 64 + lane;
    int c1 = c0 + 32;
    float v0 = a0 + bias[c0];
    float v1 = a1 + bias[c1];
    if (RES) {
        v0 += hres[(size_t)n * 512 + c0];
        v1 += hres[(size_t)n * 512 + c1];
    }
    v0 = v0 > 0.f ? v0 : expm1f(v0);
    v1 = v1 > 0.f ? v1 : expm1f(v1);
    out[(size_t)n * 512 + c0] = v0;
    out[(size_t)n * 512 + c1] = v1;
}

// ---------------- layer-2 fused GEMM: ft2 = h@W (16), res2 = h@Wres (16) -----
__global__ __launch_bounds__(256) void gemm_l2_kernel(const float* __restrict__ h,
                                                      const float* __restrict__ W,
                                                      const float* __restrict__ Wr,
                                                      float* __restrict__ ft,
                                                      float* __restrict__ res) {
    __shared__ float sh[512];
    int n = blockIdx.x;
    const float* row = h + (size_t)n * 512;
    for (int i = threadIdx.x; i < 512; i += 256) sh[i] = row[i];
    __syncthreads();
    int wid = threadIdx.x >> 5, lane = threadIdx.x & 31;
    int jbase = wid * 4;  // warps 0..3 -> ft cols, warps 4..7 -> res cols
    float p[4] = {0.f, 0.f, 0.f, 0.f};
    for (int k = lane; k < 512; k += 32) {
        float hv = sh[k];
        #pragma unroll
        for (int jj = 0; jj < 4; jj++) {
            int j = jbase + jj;
            float w = (j < 16) ? W[k * 16 + j] : Wr[k * 16 + (j - 16)];
            p[jj] += hv * w;
        }
    }
    #pragma unroll
    for (int jj = 0; jj < 4; jj++) {
        float v = p[jj];
        #pragma unroll
        for (int o = 16; o; o >>= 1) v += __shfl_xor_sync(0xffffffffu, v, o);
        if (lane == 0) {
            int j = jbase + jj;
            if (j < 16) ft[(size_t)n * 16 + j] = v;
            else        res[(size_t)n * 16 + (j - 16)] = v;
        }
    }
}

// ---------------- layer-2 aggregation: H=1 D=16, one warp per node -----------
__global__ void gat_agg_l2(const float* __restrict__ ft,
                           const float* __restrict__ el,
                           const float* __restrict__ er,
                           const float* __restrict__ res,
                           const float* __restrict__ bias,
                           float* __restrict__ out) {
    int node = blockIdx.x * 8 + (threadIdx.x >> 5);
    if (node >= N_NODES) return;
    int lane = threadIdx.x & 31;
    int s = g_off[node], e = g_off[node + 1];
    float ern = er[node];

    float m = -INFINITY, ss = 0.f;
    for (int i = s + lane; i < e; i += 32) {
        float v = lrelu(el[g_esrc[i]] + ern);
        float mn = fmaxf(m, v);
        ss = ss * expf(m - mn) + expf(v - mn);
        m = mn;
    }
    #pragma unroll
    for (int o = 16; o; o >>= 1) {
        float om = __shfl_xor_sync(0xffffffffu, m, o);
        float os = __shfl_xor_sync(0xffffffffu, ss, o);
        float mn = fmaxf(m, om);
        float sa = (m == -INFINITY) ? 0.f : ss * expf(m - mn);
        float sb = (om == -INFINITY) ? 0.f : os * expf(om - mn);
        ss = sa + sb;
        m = mn;
    }
    float inv = (e > s) ? 1.0f / ss : 0.0f;

    float acc = 0.f;
    for (int i = s; i < e; ++i) {
        int sn = g_esrc[i];
        float a = expf(lrelu(el[sn] + ern) - m) * inv;
        if (lane < 16) acc += a * ft[(size_t)sn * 16 + lane];
    }
    if (lane < 16)
        out[(size_t)node * 16 + lane] = acc + res[(size_t)node * 16 + lane] + bias[lane];
}

// ---------------- launcher ----------------------------------------------------
extern "C" void kernel_launch(void* const* d_in, const int* in_sizes, int n_in,
                              void* d_out, int out_size) {
    const float* feat0 = (const float*)d_in[0];
    const float* feat1 = (const float*)d_in[1];
    const float* fc0_w = (const float*)d_in[2];
    const float* fc0_b = (const float*)d_in[3];
    const float* fc1_w = (const float*)d_in[4];
    const float* fc1_b = (const float*)d_in[5];
    const float* l0_W  = (const float*)d_in[6];
    const float* l0_al = (const float*)d_in[7];
    const float* l0_ar = (const float*)d_in[8];
    const float* l0_b  = (const float*)d_in[9];
    const float* l1_W  = (const float*)d_in[10];
    const float* l1_al = (const float*)d_in[11];
    const float* l1_ar = (const float*)d_in[12];
    const float* l1_b  = (const float*)d_in[13];
    const float* l2_W  = (const float*)d_in[14];
    const float* l2_al = (const float*)d_in[15];
    const float* l2_ar = (const float*)d_in[16];
    const float* l2_b  = (const float*)d_in[17];
    const float* l2_rw = (const float*)d_in[18];
    const int*   src   = (const int*)d_in[19];
    const int*   dst   = (const int*)d_in[20];
    int E = in_sizes[19];

    float* pA;
    float* pB;
    float* pel;
    float* per;
    cudaGetSymbolAddress((void**)&pA, g_bufA);
    cudaGetSymbolAddress((void**)&pB, g_bufB);
    cudaGetSymbolAddress((void**)&pel, g_el);
    cudaGetSymbolAddress((void**)&per, g_er);

    float* logits = (float*)d_out;
    const size_t LOGITS = (size_t)N_NODES * 16;
    const size_t ENC    = (size_t)N_NODES * 512;
    float* encoded = ((size_t)out_size >= LOGITS + ENC) ? logits + LOGITS : pA;

    // --- CSR build ---
    zero_deg_kernel<<<(N_NODES + 255) / 256, 256>>>();
    hist_kernel<<<(E + 255) / 256, 256>>>(dst, E);
    scan_kernel<<<1, 1024>>>(N_NODES);
    scatter_kernel<<<(E + 255) / 256, 256>>>(src, dst, E);

    // --- input projections ---
    {
        dim3 g0(1, (25000 + 127) / 128);
        gemm_tf32<<<g0, 256>>>(feat0, fc0_w, fc0_b, pA, 25000, 64, 256);
        gemm_tf32<<<g0, 256>>>(feat1, fc1_w, fc1_b, pA + (size_t)25000 * 64, 25000, 64, 256);
    }

    dim3 gBig(4, (N_NODES + 127) / 128);  // N=512 tiles x M tiles

    // --- layer 0 ---
    gemm_tf32<<<gBig, 256>>>(pA, l0_W, nullptr, pB, N_NODES, 512, 64);
    attn_proj_kernel<<<(N_NODES * 8 + 7) / 8, 256>>>(pB, l0_al, l0_ar, pel, per, N_NODES, 8, 64);
    gat_agg_h8<0><<<N_NODES, 256>>>(pB, pel, per, l0_b, nullptr, pA);

    // --- layer 1 ---
    gemm_tf32<<<gBig, 256>>>(pA, l1_W, nullptr, pB, N_NODES, 512, 512);
    attn_proj_kernel<<<(N_NODES * 8 + 7) / 8, 256>>>(pB, l1_al, l1_ar, pel, per, N_NODES, 8, 64);
    gat_agg_h8<1><<<N_NODES, 256>>>(pB, pel, per, l1_b, pA, encoded);

    // --- layer 2 ---
    float* ft2  = pB;
    float* res2 = pB + LOGITS;
    gemm_l2_kernel<<<N_NODES, 256>>>(encoded, l2_W, l2_rw, ft2, res2);
    attn_proj_kernel<<<(N_NODES + 7) / 8, 256>>>(ft2, l2_al, l2_ar, pel, per, N_NODES, 1, 16);
    gat_agg_l2<<<(N_NODES + 7) / 8, 256>>>(ft2, pel, per, res2, l2_b, logits);
}

// round 3
// speedup vs baseline: 2.2764x; 1.9689x over previous
#include <cuda_runtime.h>
#include <math.h>
#include <stdint.h>

#define N_NODES 50000
#define E_MAX   500000

// ---------------- scratch (static __device__ — no allocations allowed) -------
__device__ float g_bufA[(size_t)N_NODES * 512];
__device__ float g_bufB[(size_t)N_NODES * 512 + 64];
__device__ float g_el[(size_t)N_NODES * 8];
__device__ float g_er[(size_t)N_NODES * 8];
__device__ int   g_deg[N_NODES];
__device__ int   g_off[N_NODES + 1];
__device__ int   g_pos[N_NODES];
__device__ int   g_esrc[E_MAX + 8];

// ---------------- CSR build ---------------------------------------------------
__global__ void zero_deg_kernel() {
    int i = blockIdx.x * blockDim.x + threadIdx.x;
    if (i < N_NODES) g_deg[i] = 0;
}

__global__ void hist_kernel(const int* __restrict__ dst, int E) {
    int i = blockIdx.x * blockDim.x + threadIdx.x;
    if (i < E) atomicAdd(&g_deg[dst[i]], 1);
}

__global__ void scan_kernel(int n) {
    __shared__ int wsum[32];
    __shared__ int s_carry;
    int tid = threadIdx.x;
    int lane = tid & 31, wid = tid >> 5;
    if (tid == 0) s_carry = 0;
    __syncthreads();
    for (int base = 0; base < n; base += blockDim.x) {
        int i = base + tid;
        int v = (i < n) ? g_deg[i] : 0;
        int x = v;
        #pragma unroll
        for (int o = 1; o < 32; o <<= 1) {
            int y = __shfl_up_sync(0xffffffffu, x, o);
            if (lane >= o) x += y;
        }
        if (lane == 31) wsum[wid] = x;
        __syncthreads();
        if (wid == 0) {
            int w = wsum[lane];
            #pragma unroll
            for (int o = 1; o < 32; o <<= 1) {
                int y = __shfl_up_sync(0xffffffffu, w, o);
                if (lane >= o) w += y;
            }
            wsum[lane] = w;
        }
        __syncthreads();
        int incl = x + (wid > 0 ? wsum[wid - 1] : 0);
        int c = s_carry;
        if (i < n) {
            int ex = c + incl - v;
            g_off[i] = ex;
            g_pos[i] = ex;
        }
        __syncthreads();
        if (tid == 0) s_carry = c + wsum[31];
        __syncthreads();
    }
    if (tid == 0) g_off[n] = s_carry;
}

__global__ void scatter_kernel(const int* __restrict__ src, const int* __restrict__ dst, int E) {
    int i = blockIdx.x * blockDim.x + threadIdx.x;
    if (i < E) {
        int p = atomicAdd(&g_pos[dst[i]], 1);
        g_esrc[p] = src[i];
    }
}

// ---------------- 3xTF32 tensor-core GEMM with cp.async pipeline -------------
// C[M,N] = A[M,K]@B[K,N] (+bias). BM=128 BN=128 BK=16, 256 thr, warp tile 64x32.
// Each operand split hi/lo tf32; acc += Alo*Bhi + Ahi*Blo + Ahi*Bhi (fp32 acc).
__device__ __forceinline__ uint32_t f2tf32(float x) {
    uint32_t r;
    asm("cvt.rna.tf32.f32 %0, %1;" : "=r"(r) : "f"(x));
    return r;
}

__device__ __forceinline__ void cp_async16(uint32_t dst_smem, const void* src, bool pred) {
    int sz = pred ? 16 : 0;
    asm volatile("cp.async.cg.shared.global [%0], [%1], 16, %2;"
                 :: "r"(dst_smem), "l"(src), "r"(sz));
}

__global__ __launch_bounds__(256) void gemm_3xtf32(const float* __restrict__ A,
                                                   const float* __restrict__ B,
                                                   const float* __restrict__ bias,
                                                   float* __restrict__ C,
                                                   int M, int N, int K) {
    __shared__ float As[2][128][20];   // [buf][m][k] (+4 pad)
    __shared__ float Bs[2][16][132];   // [buf][k][n] (+4 pad)
    int bm = blockIdx.y * 128;
    int bn = blockIdx.x * 128;
    int tid = threadIdx.x;
    int warp = tid >> 5, lane = tid & 31;
    int wm = (warp & 1) * 64;
    int wn = (warp >> 1) * 32;
    int g = lane >> 2, tg = lane & 3;

    uint32_t sA_base = (uint32_t)__cvta_generic_to_shared(&As[0][0][0]);
    uint32_t sB_base = (uint32_t)__cvta_generic_to_shared(&Bs[0][0][0]);

    float acc[4][4][4];
    #pragma unroll
    for (int i = 0; i < 4; i++)
        #pragma unroll
        for (int j = 0; j < 4; j++)
            #pragma unroll
            for (int r = 0; r < 4; r++) acc[i][j][r] = 0.0f;

    // per-thread load coords
    int raA[2], caA[2], raB[2], caB[2];
    #pragma unroll
    for (int i = 0; i < 2; i++) {
        int idx = tid * 2 + i;
        raA[i] = idx >> 2;  caA[i] = (idx & 3) * 4;
        raB[i] = idx >> 5;  caB[i] = (idx & 31) * 4;
    }

    auto load_tiles = [&](int buf, int k0) {
        #pragma unroll
        for (int i = 0; i < 2; i++) {
            bool p = (bm + raA[i]) < M;
            const float* gp = A + (size_t)(p ? bm + raA[i] : 0) * K + k0 + caA[i];
            uint32_t d = sA_base + (((buf * 128 + raA[i]) * 20 + caA[i]) << 2);
            cp_async16(d, gp, p);
        }
        #pragma unroll
        for (int i = 0; i < 2; i++) {
            bool p = (bn + caB[i]) < N;
            const float* gp = B + (size_t)(k0 + raB[i]) * N + (p ? bn + caB[i] : 0);
            uint32_t d = sB_base + (((buf * 16 + raB[i]) * 132 + caB[i]) << 2);
            cp_async16(d, gp, p);
        }
    };

    int nk = K >> 4;
    load_tiles(0, 0);
    asm volatile("cp.async.commit_group;");

    for (int t = 0; t < nk; ++t) {
        int buf = t & 1;
        if (t + 1 < nk) {
            load_tiles(buf ^ 1, (t + 1) << 4);
            asm volatile("cp.async.commit_group;");
            asm volatile("cp.async.wait_group 1;");
        } else {
            asm volatile("cp.async.wait_group 0;");
        }
        __syncthreads();

        #pragma unroll
        for (int kk = 0; kk < 16; kk += 8) {
            uint32_t ahi[4][4], alo[4][4];
            #pragma unroll
            for (int mt = 0; mt < 4; mt++) {
                int rb = wm + mt * 16;
                #pragma unroll
                for (int q = 0; q < 4; q++) {
                    int rr = rb + g + (q & 1) * 8;
                    int kq = kk + tg + (q >> 1) * 4;
                    float x = As[buf][rr][kq];
                    uint32_t hi = f2tf32(x);
                    float lo_f = x - __uint_as_float(hi);
                    ahi[mt][q] = hi;
                    alo[mt][q] = f2tf32(lo_f);
                }
            }
            uint32_t bhi[4][2], blo[4][2];
            #pragma unroll
            for (int nt = 0; nt < 4; nt++) {
                int cb = wn + nt * 8;
                #pragma unroll
                for (int q = 0; q < 2; q++) {
                    float x = Bs[buf][kk + tg + q * 4][cb + g];
                    uint32_t hi = f2tf32(x);
                    float lo_f = x - __uint_as_float(hi);
                    bhi[nt][q] = hi;
                    blo[nt][q] = f2tf32(lo_f);
                }
            }
            #pragma unroll
            for (int mt = 0; mt < 4; mt++)
                #pragma unroll
                for (int nt = 0; nt < 4; nt++) {
                    asm volatile(
                        "mma.sync.aligned.m16n8k8.row.col.f32.tf32.tf32.f32 "
                        "{%0,%1,%2,%3}, {%4,%5,%6,%7}, {%8,%9}, {%0,%1,%2,%3};"
                        : "+f"(acc[mt][nt][0]), "+f"(acc[mt][nt][1]),
                          "+f"(acc[mt][nt][2]), "+f"(acc[mt][nt][3])
                        : "r"(alo[mt][0]), "r"(alo[mt][1]), "r"(alo[mt][2]), "r"(alo[mt][3]),
                          "r"(bhi[nt][0]), "r"(bhi[nt][1]));
                    asm volatile(
                        "mma.sync.aligned.m16n8k8.row.col.f32.tf32.tf32.f32 "
                        "{%0,%1,%2,%3}, {%4,%5,%6,%7}, {%8,%9}, {%0,%1,%2,%3};"
                        : "+f"(acc[mt][nt][0]), "+f"(acc[mt][nt][1]),
                          "+f"(acc[mt][nt][2]), "+f"(acc[mt][nt][3])
                        : "r"(ahi[mt][0]), "r"(ahi[mt][1]), "r"(ahi[mt][2]), "r"(ahi[mt][3]),
                          "r"(blo[nt][0]), "r"(blo[nt][1]));
                    asm volatile(
                        "mma.sync.aligned.m16n8k8.row.col.f32.tf32.tf32.f32 "
                        "{%0,%1,%2,%3}, {%4,%5,%6,%7}, {%8,%9}, {%0,%1,%2,%3};"
                        : "+f"(acc[mt][nt][0]), "+f"(acc[mt][nt][1]),
                          "+f"(acc[mt][nt][2]), "+f"(acc[mt][nt][3])
                        : "r"(ahi[mt][0]), "r"(ahi[mt][1]), "r"(ahi[mt][2]), "r"(ahi[mt][3]),
                          "r"(bhi[nt][0]), "r"(bhi[nt][1]));
                }
        }
        __syncthreads();
    }

    #pragma unroll
    for (int mt = 0; mt < 4; mt++) {
        #pragma unroll
        for (int nt = 0; nt < 4; nt++) {
            int r0 = bm + wm + mt * 16 + g;
            int c0 = bn + wn + nt * 8 + 2 * tg;
            #pragma unroll
            for (int hh = 0; hh < 2; hh++) {
                int r = r0 + hh * 8;
                if (r >= M || c0 >= N) continue;
                float v0 = acc[mt][nt][hh * 2 + 0];
                float v1 = acc[mt][nt][hh * 2 + 1];
                if (bias) { v0 += bias[c0]; v1 += bias[c0 + 1]; }
                *(float2*)&C[(size_t)r * N + c0] = make_float2(v0, v1);
            }
        }
    }
}

// ---------------- attention projections: el/er = <ft[n,h,:], al/ar[h,:]> -----
__global__ void attn_proj_kernel(const float* __restrict__ ft,
                                 const float* __restrict__ al,
                                 const float* __restrict__ ar,
                                 float* __restrict__ el, float* __restrict__ er,
                                 int N, int H, int D) {
    int gw = (blockIdx.x * blockDim.x + threadIdx.x) >> 5;
    int lane = threadIdx.x & 31;
    if (gw >= N * H) return;
    int n = gw / H, h = gw % H;
    const float* f = ft + ((size_t)n * H + h) * D;
    float sl = 0.f, sr = 0.f;
    for (int d = lane; d < D; d += 32) {
        float v = f[d];
        sl += v * al[h * D + d];
        sr += v * ar[h * D + d];
    }
    #pragma unroll
    for (int o = 16; o; o >>= 1) {
        sl += __shfl_xor_sync(0xffffffffu, sl, o);
        sr += __shfl_xor_sync(0xffffffffu, sr, o);
    }
    if (lane == 0) {
        el[(size_t)n * H + h] = sl;
        er[(size_t)n * H + h] = sr;
    }
}

__device__ __forceinline__ float lrelu(float x) { return x > 0.f ? x : 0.2f * x; }

// ---------------- GAT aggregation, H=8 D=64, one block per dst node ----------
// Edge list + unnormalized exp-weights cached in smem (deg<=CAP); value loop
// unrolled x4 with float2 gathers. Fallback recompute path for deg>CAP.
template <int RES>
__global__ __launch_bounds__(256) void gat_agg_h8(const float* __restrict__ ft,
                                                  const float* __restrict__ el,
                                                  const float* __restrict__ er,
                                                  const float* __restrict__ bias,
                                                  const float* __restrict__ hres,
                                                  float* __restrict__ out) {
    constexpr int CAP = 128;
    __shared__ int   s_src[CAP];
    __shared__ float s_w[8][CAP];
    int n = blockIdx.x;
    int h = threadIdx.x >> 5;
    int lane = threadIdx.x & 31;
    int s = g_off[n], e = g_off[n + 1], deg = e - s;
    float ern = er[(size_t)n * 8 + h];

    float acc0 = 0.f, acc1 = 0.f;
    float inv = 0.f;

    if (deg <= CAP) {
        for (int i = threadIdx.x; i < deg; i += 256) s_src[i] = g_esrc[s + i];
        __syncthreads();
        float m = -INFINITY;
        for (int i = lane; i < deg; i += 32) {
            float v = lrelu(el[(size_t)s_src[i] * 8 + h] + ern);
            s_w[h][i] = v;
            m = fmaxf(m, v);
        }
        #pragma unroll
        for (int o = 16; o; o >>= 1) m = fmaxf(m, __shfl_xor_sync(0xffffffffu, m, o));
        float ssum = 0.f;
        for (int i = lane; i < deg; i += 32) {
            float ex = __expf(s_w[h][i] - m);
            s_w[h][i] = ex;
            ssum += ex;
        }
        #pragma unroll
        for (int o = 16; o; o >>= 1) ssum += __shfl_xor_sync(0xffffffffu, ssum, o);
        inv = (deg > 0) ? 1.0f / ssum : 0.0f;
        __syncwarp();

        const float* fth = ft + h * 64 + lane * 2;
        int i = 0;
        for (; i + 4 <= deg; i += 4) {
            int sn0 = s_src[i], sn1 = s_src[i + 1], sn2 = s_src[i + 2], sn3 = s_src[i + 3];
            float a0 = s_w[h][i], a1 = s_w[h][i + 1], a2 = s_w[h][i + 2], a3 = s_w[h][i + 3];
            float2 f0 = *(const float2*)&fth[(size_t)sn0 * 512];
            float2 f1 = *(const float2*)&fth[(size_t)sn1 * 512];
            float2 f2 = *(const float2*)&fth[(size_t)sn2 * 512];
            float2 f3 = *(const float2*)&fth[(size_t)sn3 * 512];
            acc0 += a0 * f0.x + a1 * f1.x + a2 * f2.x + a3 * f3.x;
            acc1 += a0 * f0.y + a1 * f1.y + a2 * f2.y + a3 * f3.y;
        }
        for (; i < deg; ++i) {
            int sn = s_src[i];
            float a = s_w[h][i];
            float2 f = *(const float2*)&fth[(size_t)sn * 512];
            acc0 += a * f.x;
            acc1 += a * f.y;
        }
    } else {
        // fallback: two-pass online softmax, recompute weights
        float m = -INFINITY, ssum = 0.f;
        for (int i = s + lane; i < e; i += 32) {
            float v = lrelu(el[(size_t)g_esrc[i] * 8 + h] + ern);
            float mn = fmaxf(m, v);
            ssum = ssum * __expf(m - mn) + __expf(v - mn);
            m = mn;
        }
        #pragma unroll
        for (int o = 16; o; o >>= 1) {
            float om = __shfl_xor_sync(0xffffffffu, m, o);
            float os = __shfl_xor_sync(0xffffffffu, ssum, o);
            float mn = fmaxf(m, om);
            float sa = (m == -INFINITY) ? 0.f : ssum * __expf(m - mn);
            float sb = (om == -INFINITY) ? 0.f : os * __expf(om - mn);
            ssum = sa + sb;
            m = mn;
        }
        inv = 1.0f / ssum;
        const float* fth = ft + h * 64 + lane * 2;
        for (int i = s; i < e; ++i) {
            int sn = g_esrc[i];
            float a = __expf(lrelu(el[(size_t)sn * 8 + h] + ern) - m);
            float2 f = *(const float2*)&fth[(size_t)sn * 512];
            acc0 += a * f.x;
            acc1 += a * f.y;
        }
    }

    int c0 = h * 64 + lane * 2;
    float v0 = acc0 * inv + bias[c0];
    float v1 = acc1 * inv + bias[c0 + 1];
    if (RES) {
        v0 += hres[(size_t)n * 512 + c0];
        v1 += hres[(size_t)n * 512 + c0 + 1];
    }
    v0 = v0 > 0.f ? v0 : expm1f(v0);
    v1 = v1 > 0.f ? v1 : expm1f(v1);
    *(float2*)&out[(size_t)n * 512 + c0] = make_float2(v0, v1);
}

// ---------------- layer-2 fused GEMM: 8 nodes/block, W staged via smem -------
__global__ __launch_bounds__(256) void gemm_l2_kernel(const float* __restrict__ h,
                                                      const float* __restrict__ W,
                                                      const float* __restrict__ Wr,
                                                      float* __restrict__ ft,
                                                      float* __restrict__ res) {
    __shared__ float sW[64][33];
    __shared__ float sh[8][64];
    int nb = blockIdx.x * 8;
    int warp = threadIdx.x >> 5, lane = threadIdx.x & 31;
    float acc = 0.f;
    for (int kc = 0; kc < 512; kc += 64) {
        __syncthreads();
        #pragma unroll
        for (int i = 0; i < 8; i++) {
            int idx = threadIdx.x + i * 256;  // 2048 = 64x32
            int r = idx >> 5, c = idx & 31;
            sW[r][c] = (c < 16) ? W[(kc + r) * 16 + c] : Wr[(kc + r) * 16 + (c - 16)];
        }
        #pragma unroll
        for (int i = 0; i < 2; i++) {
            int idx = threadIdx.x + i * 256;  // 512 = 8x64
            int node = idx >> 6, k = idx & 63;
            sh[node][k] = h[(size_t)(nb + node) * 512 + kc + k];
        }
        __syncthreads();
        #pragma unroll
        for (int k = 0; k < 64; k++)
            acc += sh[warp][k] * sW[k][lane];
    }
    int node = nb + warp;
    if (lane < 16) ft[(size_t)node * 16 + lane] = acc;
    else           res[(size_t)node * 16 + (lane - 16)] = acc;
}

// ---------------- layer-2 aggregation: H=1 D=16, one warp per node -----------
__global__ void gat_agg_l2(const float* __restrict__ ft,
                           const float* __restrict__ el,
                           const float* __restrict__ er,
                           const float* __restrict__ res,
                           const float* __restrict__ bias,
                           float* __restrict__ out) {
    int node = blockIdx.x * 8 + (threadIdx.x >> 5);
    if (node >= N_NODES) return;
    int lane = threadIdx.x & 31;
    int s = g_off[node], e = g_off[node + 1];
    float ern = er[node];

    float m = -INFINITY, ss = 0.f;
    for (int i = s + lane; i < e; i += 32) {
        float v = lrelu(el[g_esrc[i]] + ern);
        float mn = fmaxf(m, v);
        ss = ss * __expf(m - mn) + __expf(v - mn);
        m = mn;
    }
    #pragma unroll
    for (int o = 16; o; o >>= 1) {
        float om = __shfl_xor_sync(0xffffffffu, m, o);
        float os = __shfl_xor_sync(0xffffffffu, ss, o);
        float mn = fmaxf(m, om);
        float sa = (m == -INFINITY) ? 0.f : ss * __expf(m - mn);
        float sb = (om == -INFINITY) ? 0.f : os * __expf(om - mn);
        ss = sa + sb;
        m = mn;
    }
    float inv = (e > s) ? 1.0f / ss : 0.0f;

    float acc = 0.f;
    for (int i = s; i < e; ++i) {
        int sn = g_esrc[i];
        float a = __expf(lrelu(el[sn] + ern) - m) * inv;
        if (lane < 16) acc += a * ft[(size_t)sn * 16 + lane];
    }
    if (lane < 16)
        out[(size_t)node * 16 + lane] = acc + res[(size_t)node * 16 + lane] + bias[lane];
}

// ---------------- launcher ----------------------------------------------------
extern "C" void kernel_launch(void* const* d_in, const int* in_sizes, int n_in,
                              void* d_out, int out_size) {
    const float* feat0 = (const float*)d_in[0];
    const float* feat1 = (const float*)d_in[1];
    const float* fc0_w = (const float*)d_in[2];
    const float* fc0_b = (const float*)d_in[3];
    const float* fc1_w = (const float*)d_in[4];
    const float* fc1_b = (const float*)d_in[5];
    const float* l0_W  = (const float*)d_in[6];
    const float* l0_al = (const float*)d_in[7];
    const float* l0_ar = (const float*)d_in[8];
    const float* l0_b  = (const float*)d_in[9];
    const float* l1_W  = (const float*)d_in[10];
    const float* l1_al = (const float*)d_in[11];
    const float* l1_ar = (const float*)d_in[12];
    const float* l1_b  = (const float*)d_in[13];
    const float* l2_W  = (const float*)d_in[14];
    const float* l2_al = (const float*)d_in[15];
    const float* l2_ar = (const float*)d_in[16];
    const float* l2_b  = (const float*)d_in[17];
    const float* l2_rw = (const float*)d_in[18];
    const int*   src   = (const int*)d_in[19];
    const int*   dst   = (const int*)d_in[20];
    int E = in_sizes[19];

    float* pA;
    float* pB;
    float* pel;
    float* per;
    cudaGetSymbolAddress((void**)&pA, g_bufA);
    cudaGetSymbolAddress((void**)&pB, g_bufB);
    cudaGetSymbolAddress((void**)&pel, g_el);
    cudaGetSymbolAddress((void**)&per, g_er);

    float* logits = (float*)d_out;
    const size_t LOGITS = (size_t)N_NODES * 16;
    const size_t ENC    = (size_t)N_NODES * 512;
    float* encoded = ((size_t)out_size >= LOGITS + ENC) ? logits + LOGITS : pA;

    // --- CSR build ---
    zero_deg_kernel<<<(N_NODES + 255) / 256, 256>>>();
    hist_kernel<<<(E + 255) / 256, 256>>>(dst, E);
    scan_kernel<<<1, 1024>>>(N_NODES);
    scatter_kernel<<<(E + 255) / 256, 256>>>(src, dst, E);

    // --- input projections ---
    {
        dim3 g0(1, (25000 + 127) / 128);
        gemm_3xtf32<<<g0, 256>>>(feat0, fc0_w, fc0_b, pA, 25000, 64, 256);
        gemm_3xtf32<<<g0, 256>>>(feat1, fc1_w, fc1_b, pA + (size_t)25000 * 64, 25000, 64, 256);
    }

    dim3 gBig(4, (N_NODES + 127) / 128);

    // --- layer 0 ---
    gemm_3xtf32<<<gBig, 256>>>(pA, l0_W, nullptr, pB, N_NODES, 512, 64);
    attn_proj_kernel<<<(N_NODES * 8 + 7) / 8, 256>>>(pB, l0_al, l0_ar, pel, per, N_NODES, 8, 64);
    gat_agg_h8<0><<<N_NODES, 256>>>(pB, pel, per, l0_b, nullptr, pA);

    // --- layer 1 ---
    gemm_3xtf32<<<gBig, 256>>>(pA, l1_W, nullptr, pB, N_NODES, 512, 512);
    attn_proj_kernel<<<(N_NODES * 8 + 7) / 8, 256>>>(pB, l1_al, l1_ar, pel, per, N_NODES, 8, 64);
    gat_agg_h8<1><<<N_NODES, 256>>>(pB, pel, per, l1_b, pA, encoded);

    // --- layer 2 ---
    float* ft2  = pB;
    float* res2 = pB + LOGITS;
    gemm_l2_kernel<<<N_NODES / 8, 256>>>(encoded, l2_W, l2_rw, ft2, res2);
    attn_proj_kernel<<<(N_NODES + 7) / 8, 256>>>(ft2, l2_al, l2_ar, pel, per, N_NODES, 1, 16);
    gat_agg_l2<<<(N_NODES + 7) / 8, 256>>>(ft2, pel, per, res2, l2_b, logits);
}